// round 11
// baseline (speedup 1.0000x reference)
#include <cuda_runtime.h>
#include <cuda_bf16.h>
#include <cstdint>

// ---------------------------------------------------------------------------
// SparseGraphSAGE on GB300 — round 11.
//   One persistent pipelined GEMM kernel (used for all 4 node-GEMMs):
//     - 148 persistent CTAs, 512 thr; W(hi/lo) cp.async'd once per CTA;
//     - fp32 A tile cp.async-prefetched into a stage buffer during MMA of
//       the previous tile; convert (bf16 split) smem->smem per tile.
//   spmm/build/decode unchanged (spmm at LTS cap).
// ---------------------------------------------------------------------------

#define NN_MAX 50000
#define CAP 64

__device__ int   g_cnt[NN_MAX];
__device__ int   g_col[NN_MAX * CAP];
__device__ float g_val[NN_MAX * CAP];
__device__ float g_deginv[NN_MAX];
__device__ __align__(16) float g_t [NN_MAX * 128];
__device__ __align__(16) float g_h1[NN_MAX * 128];
__device__ __align__(16) float g_P [NN_MAX * 128];
__device__ __align__(16) float g_Q [NN_MAX * 128];

// pre-split, pre-transposed weights [n][k]: 0=W1, 1=W2, 2=Wd1_top, 3=Wd1_bot
__device__ __align__(16) __nv_bfloat16 g_Whi[4][16384];
__device__ __align__(16) __nv_bfloat16 g_Wlo[4][16384];

// ------------------------------ helpers ------------------------------------
__device__ __forceinline__ uint32_t smem_u32(const void* p) {
    uint32_t a;
    asm("{ .reg .u64 t; cvta.to.shared.u64 t, %1; cvt.u32.u64 %0, t; }"
        : "=r"(a) : "l"(p));
    return a;
}
__device__ __forceinline__ void ldsm_x4(uint32_t addr, uint32_t r[4]) {
    asm volatile("ldmatrix.sync.aligned.m8n8.x4.shared.b16 {%0,%1,%2,%3}, [%4];"
                 : "=r"(r[0]), "=r"(r[1]), "=r"(r[2]), "=r"(r[3]) : "r"(addr));
}
__device__ __forceinline__ void mma16816(float* c, const uint32_t* a,
                                         uint32_t b0, uint32_t b1) {
    asm volatile("mma.sync.aligned.m16n8k16.row.col.f32.bf16.bf16.f32 "
        "{%0,%1,%2,%3}, {%4,%5,%6,%7}, {%8,%9}, {%0,%1,%2,%3};"
        : "+f"(c[0]), "+f"(c[1]), "+f"(c[2]), "+f"(c[3])
        : "r"(a[0]), "r"(a[1]), "r"(a[2]), "r"(a[3]), "r"(b0), "r"(b1));
}
__device__ __forceinline__ void cp16(uint32_t saddr, const void* g) {
    asm volatile("cp.async.cg.shared.global [%0], [%1], 16;"
                 :: "r"(saddr), "l"(g) : "memory");
}
#define CP_COMMIT() asm volatile("cp.async.commit_group;" ::: "memory")
#define CP_WAIT0()  asm volatile("cp.async.wait_group 0;" ::: "memory")

__device__ __forceinline__ uint32_t pack_hi2(float x, float y, float& rx, float& ry) {
    __nv_bfloat16 hx = __float2bfloat16(x), hy = __float2bfloat16(y);
    rx = x - __bfloat162float(hx);
    ry = y - __bfloat162float(hy);
    return ((uint32_t)__bfloat16_as_ushort(hy) << 16) | __bfloat16_as_ushort(hx);
}
__device__ __forceinline__ uint32_t pack_lo2(float rx, float ry) {
    __nv_bfloat16 lx = __float2bfloat16(rx), ly = __float2bfloat16(ry);
    return ((uint32_t)__bfloat16_as_ushort(ly) << 16) | __bfloat16_as_ushort(lx);
}

// ------------------------------ smem geometry ------------------------------
#define PITCH 136
#define ROWB  (PITCH * 2)            // 272 bytes per padded row
#define TILE_B (128 * ROWB)          // 34816
#define SM_AHI   0
#define SM_ALO   34816
#define SM_WHI   69632
#define SM_WLO   104448
#define SM_STAGE 139264              // fp32 A tile stage, 65536 B
#define SMEM_P   204800
#define GT 512

// 3-pass split MMA (hi*hi + hi*lo + lo*hi); warp tile 32m x 32n
__device__ __forceinline__ void mma_passes(uint32_t sb, int m_off, int n_off,
                                           int lane, float acc[2][4][4]) {
    const uint32_t aoff[3] = {SM_AHI, SM_AHI, SM_ALO};
    const uint32_t woff[3] = {SM_WHI, SM_WLO, SM_WHI};
    uint32_t a_r = lane & 15;
    uint32_t a_k = (lane >> 4) << 3;
    uint32_t b_r = (lane & 7) | ((lane & 16) >> 1);
    uint32_t b_k = lane & 8;
#pragma unroll
    for (int p = 0; p < 3; p++) {
        uint32_t addrA = sb + aoff[p] + (m_off + a_r) * ROWB + a_k * 2;
        uint32_t addrB = sb + woff[p] + (n_off + b_r) * ROWB + b_k * 2;
#pragma unroll
        for (int ks = 0; ks < 8; ks++) {
            uint32_t a[2][4];
            ldsm_x4(addrA,             a[0]);
            ldsm_x4(addrA + 16 * ROWB, a[1]);
            uint32_t b[2][4];
#pragma unroll
            for (int nt = 0; nt < 2; nt++)
                ldsm_x4(addrB + nt * 16 * ROWB, b[nt]);
#pragma unroll
            for (int mi = 0; mi < 2; mi++)
#pragma unroll
                for (int nt = 0; nt < 2; nt++) {
                    mma16816(acc[mi][2 * nt],     a[mi], b[nt][0], b[nt][1]);
                    mma16816(acc[mi][2 * nt + 1], a[mi], b[nt][2], b[nt][3]);
                }
            addrA += 32;
            addrB += 32;
        }
    }
}

#define ZERO_ACC(acc)                                        \
    _Pragma("unroll")                                        \
    for (int mi = 0; mi < 2; mi++)                           \
        _Pragma("unroll")                                    \
        for (int ni = 0; ni < 4; ni++)                       \
            _Pragma("unroll")                                \
            for (int j = 0; j < 4; j++) (acc)[mi][ni][j] = 0.f;

// issue cp.async for one fp32 A tile (rows clamped) into SM_STAGE
__device__ __forceinline__ void stage_A(uint32_t sb, const float4* __restrict__ A4,
                                        int m_base, int M, int tid) {
#pragma unroll
    for (int i = 0; i < 8; i++) {
        int idx = i * GT + tid;           // 0..4095 float4
        int ml = idx >> 5, q = idx & 31;
        int gm = m_base + ml; if (gm >= M) gm = M - 1;
        cp16(sb + SM_STAGE + idx * 16, A4 + (size_t)gm * 32 + q);
    }
}

// ------------------------------ weight prep --------------------------------
__global__ void k_prep(const float* __restrict__ W1, const float* __restrict__ W2,
                       const float* __restrict__ Wd1) {
    int idx = blockIdx.x * blockDim.x + threadIdx.x;
    if (idx >= 4 * 16384) return;
    int mat = idx >> 14, e = idx & 16383;
    int n = e >> 7, k = e & 127;
    float x;
    if      (mat == 0) x = W1[k * 128 + n];
    else if (mat == 1) x = W2[k * 128 + n];
    else if (mat == 2) x = Wd1[k * 128 + n];
    else               x = Wd1[(128 + k) * 128 + n];
    __nv_bfloat16 hi = __float2bfloat16(x);
    float r = x - __bfloat162float(hi);
    g_Whi[mat][n * 128 + k] = hi;
    g_Wlo[mat][n * 128 + k] = __float2bfloat16(r);
}

// --------------------- persistent pipelined GEMM ----------------------------
// C[M,128] = f((A * scale?) @ W + bias?), f = relu?
template <bool RELU, bool SCALE, bool BIAS>
__global__ __launch_bounds__(GT)
void k_gemm_pers(const float4* __restrict__ A4, const float* __restrict__ scale,
                 const __nv_bfloat16* __restrict__ wh,
                 const __nv_bfloat16* __restrict__ wl,
                 const float* __restrict__ bias, float* __restrict__ C,
                 int M, int ntiles) {
    extern __shared__ char smem[];
    uint32_t sb = smem_u32(smem);
    int tid = threadIdx.x, wid = tid >> 5, lane = tid & 31;
    int m_off = (wid & 3) * 32, n_off = (wid >> 2) * 32;
    int gid = lane >> 2, tig = lane & 3;

    // prologue: stage W (padded layout) + first A tile via cp.async
    {
        const float4* sh = (const float4*)wh;
        const float4* sl = (const float4*)wl;
#pragma unroll
        for (int i = 0; i < 4; i++) {
            int idx = i * GT + tid;       // 0..2047 float4
            int n = idx >> 4, f = idx & 15;
            uint32_t off = n * ROWB + f * 16;
            cp16(sb + SM_WHI + off, sh + idx);
            cp16(sb + SM_WLO + off, sl + idx);
        }
    }
    stage_A(sb, A4, blockIdx.x * 128, M, tid);
    CP_COMMIT();
    CP_WAIT0();
    __syncthreads();

    for (int t = blockIdx.x; t < ntiles; t += gridDim.x) {
        int m_base = t * 128;

        // convert staged fp32 tile -> bf16 hi/lo padded tiles
#pragma unroll
        for (int i = 0; i < 8; i++) {
            int idx = i * GT + tid;
            int ml = idx >> 5, q = idx & 31;
            float4 v = *(const float4*)(smem + SM_STAGE + idx * 16);
            if (SCALE) {
                int gm = m_base + ml; if (gm >= M) gm = M - 1;
                float s = scale[gm];
                v.x *= s; v.y *= s; v.z *= s; v.w *= s;
            }
            float r0, r1, r2, r3;
            uint32_t hp0 = pack_hi2(v.x, v.y, r0, r1);
            uint32_t hp1 = pack_hi2(v.z, v.w, r2, r3);
            uint32_t lp0 = pack_lo2(r0, r1);
            uint32_t lp1 = pack_lo2(r2, r3);
            uint32_t off = ml * ROWB + q * 8;
            *(uint2*)(smem + SM_AHI + off) = make_uint2(hp0, hp1);
            *(uint2*)(smem + SM_ALO + off) = make_uint2(lp0, lp1);
        }
        __syncthreads();

        // prefetch next tile's fp32 A during MMA
        int nx = t + gridDim.x;
        if (nx < ntiles) stage_A(sb, A4, nx * 128, M, tid);
        CP_COMMIT();

        float acc[2][4][4];
        ZERO_ACC(acc);
        mma_passes(sb, m_off, n_off, lane, acc);

        // epilogue
#pragma unroll
        for (int ni = 0; ni < 4; ni++) {
            int col = n_off + ni * 8 + tig * 2;
            float2 bb = make_float2(0.f, 0.f);
            if (BIAS) bb = *(const float2*)&bias[col];
#pragma unroll
            for (int mi = 0; mi < 2; mi++) {
                int r0 = m_base + m_off + mi * 16 + gid;
                float* c = acc[mi][ni];
                float v0 = c[0] + bb.x, v1 = c[1] + bb.y;
                float v2 = c[2] + bb.x, v3 = c[3] + bb.y;
                if (RELU) {
                    v0 = fmaxf(v0, 0.f); v1 = fmaxf(v1, 0.f);
                    v2 = fmaxf(v2, 0.f); v3 = fmaxf(v3, 0.f);
                }
                if (r0 < M)     *(float2*)&C[(size_t)r0 * 128 + col] = make_float2(v0, v1);
                if (r0 + 8 < M) *(float2*)&C[(size_t)(r0 + 8) * 128 + col] = make_float2(v2, v3);
            }
        }

        CP_WAIT0();       // next tile's stage complete
        __syncthreads();  // all epilogue/convert readers done before reuse
    }
}

// -------------------------------- graph prep -------------------------------
__global__ void k_build(const int2* __restrict__ idx, const float* __restrict__ val, int ne) {
    int e = blockIdx.x * blockDim.x + threadIdx.x;
    if (e >= ne) return;
    int2 rc = idx[e];
    float v = val[e];
    int slot = atomicAdd(&g_cnt[rc.x], 1);
    if (slot < CAP) {
        g_col[rc.x * CAP + slot] = rc.y;
        g_val[rc.x * CAP + slot] = v;
    }
}

__global__ void k_spmm(const float4* __restrict__ X, float4* __restrict__ Y,
                       float* __restrict__ deginv_out, int nn) {
    int w = (blockIdx.x * blockDim.x + threadIdx.x) >> 5;
    int lane = threadIdx.x & 31;
    if (w >= nn) return;
    int cnt = g_cnt[w];
    if (cnt > CAP) cnt = CAP;
    const int*   cols = &g_col[w * CAP];
    const float* vals = &g_val[w * CAP];
    float4 acc = make_float4(0.f, 0.f, 0.f, 0.f);
    float dsum = 0.f;
#pragma unroll 2
    for (int e = 0; e < cnt; e++) {
        int c = cols[e];
        float v = vals[e];
        float4 x = X[(size_t)c * 32 + lane];
        acc.x += v * x.x; acc.y += v * x.y; acc.z += v * x.z; acc.w += v * x.w;
        dsum += v;
    }
    Y[(size_t)w * 32 + lane] = acc;
    if (deginv_out != nullptr && lane == 0)
        deginv_out[w] = 1.0f / fmaxf(dsum, 1.0f);
}

// -------------------------------- decoder ----------------------------------
__global__ void k_decode2(const int* __restrict__ pu, const int* __restrict__ pv,
                          const int* __restrict__ nu, const int* __restrict__ nv,
                          const float4* __restrict__ P, const float4* __restrict__ Q,
                          const float* __restrict__ bd1, const float* __restrict__ Wd2,
                          const float* __restrict__ bd2, float* __restrict__ out, int NP) {
    int w = (blockIdx.x * blockDim.x + threadIdx.x) >> 5;
    int lane = threadIdx.x & 31;
    if (w >= 2 * NP) return;
    int u, v;
    if (w < NP) { u = pu[w]; v = pv[w]; }
    else        { u = nu[w - NP]; v = nv[w - NP]; }
    float4 p = P[(size_t)u * 32 + lane];
    float4 q = Q[(size_t)v * 32 + lane];
    float4 b = ((const float4*)bd1)[lane];
    float4 d = ((const float4*)Wd2)[lane];
    float h0 = fmaxf(p.x + q.x + b.x, 0.f);
    float h1 = fmaxf(p.y + q.y + b.y, 0.f);
    float h2 = fmaxf(p.z + q.z + b.z, 0.f);
    float h3 = fmaxf(p.w + q.w + b.w, 0.f);
    float s = h0 * d.x + h1 * d.y + h2 * d.z + h3 * d.w;
#pragma unroll
    for (int o = 16; o > 0; o >>= 1)
        s += __shfl_down_sync(0xffffffff, s, o);
    if (lane == 0) out[w] = s + bd2[0];
}

// -------------------------------- launcher ---------------------------------
extern "C" void kernel_launch(void* const* d_in, const int* in_sizes, int n_in,
                              void* d_out, int out_size) {
    int o = (n_in >= 16) ? 1 : 0;

    const int2*  adj   = (const int2*) d_in[0];
    const float* avals = (const float*)d_in[1];
    const float* h     = (const float*)d_in[2 + o];
    const int*   pos_u = (const int*)  d_in[3 + o];
    const int*   pos_v = (const int*)  d_in[4 + o];
    const int*   neg_u = (const int*)  d_in[5 + o];
    const int*   neg_v = (const int*)  d_in[6 + o];
    const float* W1    = (const float*)d_in[7 + o];
    const float* b1    = (const float*)d_in[8 + o];
    const float* W2    = (const float*)d_in[9 + o];
    const float* b2    = (const float*)d_in[10 + o];
    const float* Wd1   = (const float*)d_in[11 + o];
    const float* bd1   = (const float*)d_in[12 + o];
    const float* Wd2   = (const float*)d_in[13 + o];
    const float* bd2   = (const float*)d_in[14 + o];

    const int NE = in_sizes[1];
    const int NN = in_sizes[2 + o] / 128;
    const int NP = in_sizes[3 + o];

    float* out = (float*)d_out;
    float* pos_out = out;
    float* h2      = out + 2 * NP;

    static float* p_t = nullptr;
    static float* p_h1 = nullptr;
    static float* p_P = nullptr;
    static float* p_Q = nullptr;
    static float* p_deginv = nullptr;
    static int*   p_cnt = nullptr;
    static __nv_bfloat16* p_whi = nullptr;
    static __nv_bfloat16* p_wlo = nullptr;
    static bool init = false;
    if (!init) {
        cudaGetSymbolAddress((void**)&p_t, g_t);
        cudaGetSymbolAddress((void**)&p_h1, g_h1);
        cudaGetSymbolAddress((void**)&p_P, g_P);
        cudaGetSymbolAddress((void**)&p_Q, g_Q);
        cudaGetSymbolAddress((void**)&p_deginv, g_deginv);
        cudaGetSymbolAddress((void**)&p_cnt, g_cnt);
        cudaGetSymbolAddress((void**)&p_whi, g_Whi);
        cudaGetSymbolAddress((void**)&p_wlo, g_Wlo);
        cudaFuncSetAttribute(k_gemm_pers<true,  true,  true >,
                             cudaFuncAttributeMaxDynamicSharedMemorySize, SMEM_P);
        cudaFuncSetAttribute(k_gemm_pers<false, true,  true >,
                             cudaFuncAttributeMaxDynamicSharedMemorySize, SMEM_P);
        cudaFuncSetAttribute(k_gemm_pers<false, false, false>,
                             cudaFuncAttributeMaxDynamicSharedMemorySize, SMEM_P);
        init = true;
    }

    int ntiles = (NN + 127) / 128;
    int pgrid = ntiles < 148 ? ntiles : 148;

    cudaMemsetAsync(p_cnt, 0, (size_t)NN * sizeof(int));
    k_build<<<(NE + 255) / 256, 256>>>(adj, avals, NE);
    k_prep<<<(4 * 16384 + 255) / 256, 256>>>(W1, W2, Wd1);
    k_spmm<<<(NN * 32 + 255) / 256, 256>>>((const float4*)h, (float4*)p_t, p_deginv, NN);
    // h1 = relu((t*deginv)@W1 + b1)
    k_gemm_pers<true, true, true><<<pgrid, GT, SMEM_P>>>(
        (const float4*)p_t, p_deginv, p_whi + 0 * 16384, p_wlo + 0 * 16384,
        b1, p_h1, NN, ntiles);
    k_spmm<<<(NN * 32 + 255) / 256, 256>>>((const float4*)p_h1, (float4*)p_t, nullptr, NN);
    // h2 = (t*deginv)@W2 + b2
    k_gemm_pers<false, true, true><<<pgrid, GT, SMEM_P>>>(
        (const float4*)p_t, p_deginv, p_whi + 1 * 16384, p_wlo + 1 * 16384,
        b2, h2, NN, ntiles);
    // P = h2 @ Wd1_top
    k_gemm_pers<false, false, false><<<pgrid, GT, SMEM_P>>>(
        (const float4*)h2, nullptr, p_whi + 2 * 16384, p_wlo + 2 * 16384,
        nullptr, p_P, NN, ntiles);
    // Q = h2 @ Wd1_bot
    k_gemm_pers<false, false, false><<<pgrid, GT, SMEM_P>>>(
        (const float4*)h2, nullptr, p_whi + 3 * 16384, p_wlo + 3 * 16384,
        nullptr, p_Q, NN, ntiles);
    k_decode2<<<(2 * NP * 32 + 255) / 256, 256>>>(pos_u, pos_v, neg_u, neg_v,
                                                  (const float4*)p_P, (const float4*)p_Q,
                                                  bd1, Wd2, bd2, pos_out, NP);
}

// round 12
// speedup vs baseline: 1.2217x; 1.2217x over previous
#include <cuda_runtime.h>
#include <cuda_bf16.h>
#include <cstdint>

// ---------------------------------------------------------------------------
// SparseGraphSAGE on GB300 — round 12.
//   R10 structure (best) + merged precision passes in the MMA mainloop:
//   per ks-step load a_hi/a_lo/w_hi/w_lo once (8 ldsm) and issue all 24 MMAs
//   (hi*hi + hi*lo + lo*hi) -> 33% less LDSM traffic, 3x ILP per load batch.
// ---------------------------------------------------------------------------

#define NN_MAX 50000
#define CAP 64

__device__ int   g_cnt[NN_MAX];
__device__ int   g_col[NN_MAX * CAP];
__device__ float g_val[NN_MAX * CAP];
__device__ float g_deginv[NN_MAX];
__device__ __align__(16) float g_t [NN_MAX * 128];
__device__ __align__(16) float g_h1[NN_MAX * 128];
__device__ __align__(16) float g_P [NN_MAX * 128];
__device__ __align__(16) float g_Q [NN_MAX * 128];

// pre-split, pre-transposed weights [n][k]: 0=W1, 1=W2, 2=Wd1_top, 3=Wd1_bot
__device__ __align__(16) __nv_bfloat16 g_Whi[4][16384];
__device__ __align__(16) __nv_bfloat16 g_Wlo[4][16384];

// ------------------------------ helpers ------------------------------------
__device__ __forceinline__ uint32_t smem_u32(const void* p) {
    uint32_t a;
    asm("{ .reg .u64 t; cvta.to.shared.u64 t, %1; cvt.u32.u64 %0, t; }"
        : "=r"(a) : "l"(p));
    return a;
}
__device__ __forceinline__ void ldsm_x4(uint32_t addr, uint32_t r[4]) {
    asm volatile("ldmatrix.sync.aligned.m8n8.x4.shared.b16 {%0,%1,%2,%3}, [%4];"
                 : "=r"(r[0]), "=r"(r[1]), "=r"(r[2]), "=r"(r[3]) : "r"(addr));
}
__device__ __forceinline__ void mma16816(float* c, const uint32_t* a,
                                         uint32_t b0, uint32_t b1) {
    asm volatile("mma.sync.aligned.m16n8k16.row.col.f32.bf16.bf16.f32 "
        "{%0,%1,%2,%3}, {%4,%5,%6,%7}, {%8,%9}, {%0,%1,%2,%3};"
        : "+f"(c[0]), "+f"(c[1]), "+f"(c[2]), "+f"(c[3])
        : "r"(a[0]), "r"(a[1]), "r"(a[2]), "r"(a[3]), "r"(b0), "r"(b1));
}
__device__ __forceinline__ uint32_t pack_hi2(float x, float y, float& rx, float& ry) {
    __nv_bfloat16 hx = __float2bfloat16(x), hy = __float2bfloat16(y);
    rx = x - __bfloat162float(hx);
    ry = y - __bfloat162float(hy);
    return ((uint32_t)__bfloat16_as_ushort(hy) << 16) | __bfloat16_as_ushort(hx);
}
__device__ __forceinline__ uint32_t pack_lo2(float rx, float ry) {
    __nv_bfloat16 lx = __float2bfloat16(rx), ly = __float2bfloat16(ry);
    return ((uint32_t)__bfloat16_as_ushort(ly) << 16) | __bfloat16_as_ushort(lx);
}

// ------------------------------ smem geometry ------------------------------
#define PITCH 136
#define ROWB  (PITCH * 2)
#define TILE_B (128 * ROWB)          // 34816 B
#define SM_AHI 0
#define SM_ALO (TILE_B)
#define SM_W0HI (2 * TILE_B)
#define SM_W0LO (3 * TILE_B)
#define SM_W1HI (4 * TILE_B)
#define SM_W1LO (5 * TILE_B)
#define SMEM_G1 (4 * TILE_B)
#define SMEM_G3 (6 * TILE_B)
#define GT 512

__device__ __forceinline__ void load_W(char* smem, uint32_t dhi, uint32_t dlo,
                                       const __nv_bfloat16* __restrict__ wh,
                                       const __nv_bfloat16* __restrict__ wl, int tid) {
    const float4* sh = (const float4*)wh;
    const float4* sl = (const float4*)wl;
#pragma unroll
    for (int i = 0; i < 4; i++) {
        int idx = i * GT + tid;
        int n = idx >> 4, f = idx & 15;
        uint32_t off = n * ROWB + f * 16;
        *(float4*)(smem + dhi + off) = sh[idx];
        *(float4*)(smem + dlo + off) = sl[idx];
    }
}

__device__ __forceinline__ void split_A(char* smem, const float4* __restrict__ A4,
                                        const float* __restrict__ scale,
                                        int m_base, int M, int tid) {
#pragma unroll
    for (int i = 0; i < 8; i++) {
        int idx = i * GT + tid;
        int ml = idx >> 5, q = idx & 31;
        int gm = m_base + ml; if (gm >= M) gm = M - 1;
        float4 v = A4[(size_t)gm * 32 + q];
        if (scale) { float s = scale[gm]; v.x *= s; v.y *= s; v.z *= s; v.w *= s; }
        float r0, r1, r2, r3;
        uint32_t hp0 = pack_hi2(v.x, v.y, r0, r1);
        uint32_t hp1 = pack_hi2(v.z, v.w, r2, r3);
        uint32_t lp0 = pack_lo2(r0, r1);
        uint32_t lp1 = pack_lo2(r2, r3);
        uint32_t off = ml * ROWB + q * 8;
        *(uint2*)(smem + SM_AHI + off) = make_uint2(hp0, hp1);
        *(uint2*)(smem + SM_ALO + off) = make_uint2(lp0, lp1);
    }
}

// merged 3-product MMA mainloop: per ks load a_hi/a_lo/w_hi/w_lo, 24 MMAs
__device__ __forceinline__ void mma_merged(uint32_t sb, uint32_t whi, uint32_t wlo,
                                           int m_off, int n_off,
                                           int lane, float acc[2][4][4]) {
    uint32_t a_r = lane & 15;
    uint32_t a_k = (lane >> 4) << 3;
    uint32_t b_r = (lane & 7) | ((lane & 16) >> 1);
    uint32_t b_k = lane & 8;
    uint32_t aH = sb + SM_AHI + (m_off + a_r) * ROWB + a_k * 2;
    uint32_t aL = sb + SM_ALO + (m_off + a_r) * ROWB + a_k * 2;
    uint32_t bH = sb + whi + (n_off + b_r) * ROWB + b_k * 2;
    uint32_t bL = sb + wlo + (n_off + b_r) * ROWB + b_k * 2;
#pragma unroll
    for (int ks = 0; ks < 8; ks++) {
        uint32_t ah[2][4], al[2][4];
        ldsm_x4(aH,             ah[0]);
        ldsm_x4(aH + 16 * ROWB, ah[1]);
        ldsm_x4(aL,             al[0]);
        ldsm_x4(aL + 16 * ROWB, al[1]);
        uint32_t wh[2][4], wl[2][4];
        ldsm_x4(bH,             wh[0]);
        ldsm_x4(bH + 16 * ROWB, wh[1]);
        ldsm_x4(bL,             wl[0]);
        ldsm_x4(bL + 16 * ROWB, wl[1]);
#pragma unroll
        for (int mi = 0; mi < 2; mi++)
#pragma unroll
            for (int nt = 0; nt < 2; nt++) {
                // hi*hi
                mma16816(acc[mi][2 * nt],     ah[mi], wh[nt][0], wh[nt][1]);
                mma16816(acc[mi][2 * nt + 1], ah[mi], wh[nt][2], wh[nt][3]);
                // hi*lo
                mma16816(acc[mi][2 * nt],     ah[mi], wl[nt][0], wl[nt][1]);
                mma16816(acc[mi][2 * nt + 1], ah[mi], wl[nt][2], wl[nt][3]);
                // lo*hi
                mma16816(acc[mi][2 * nt],     al[mi], wh[nt][0], wh[nt][1]);
                mma16816(acc[mi][2 * nt + 1], al[mi], wh[nt][2], wh[nt][3]);
            }
        aH += 32; aL += 32; bH += 32; bL += 32;
    }
}

#define ZERO_ACC(acc)                                        \
    _Pragma("unroll")                                        \
    for (int mi = 0; mi < 2; mi++)                           \
        _Pragma("unroll")                                    \
        for (int ni = 0; ni < 4; ni++)                       \
            _Pragma("unroll")                                \
            for (int j = 0; j < 4; j++) (acc)[mi][ni][j] = 0.f;

// ------------------------------ weight prep --------------------------------
__global__ void k_prep(const float* __restrict__ W1, const float* __restrict__ W2,
                       const float* __restrict__ Wd1) {
    int idx = blockIdx.x * blockDim.x + threadIdx.x;
    if (idx >= 4 * 16384) return;
    int mat = idx >> 14, e = idx & 16383;
    int n = e >> 7, k = e & 127;
    float x;
    if      (mat == 0) x = W1[k * 128 + n];
    else if (mat == 1) x = W2[k * 128 + n];
    else if (mat == 2) x = Wd1[k * 128 + n];
    else               x = Wd1[(128 + k) * 128 + n];
    __nv_bfloat16 hi = __float2bfloat16(x);
    float r = x - __bfloat162float(hi);
    g_Whi[mat][n * 128 + k] = hi;
    g_Wlo[mat][n * 128 + k] = __float2bfloat16(r);
}

// ------------------------------ gemm1 (mma) --------------------------------
__global__ __launch_bounds__(GT)
void k_gemm1_mma(const float4* __restrict__ A4, const float* __restrict__ scale,
                 const float* __restrict__ bias, float* __restrict__ C, int M) {
    extern __shared__ char smem[];
    uint32_t sb = smem_u32(smem);
    int tid = threadIdx.x, wid = tid >> 5, lane = tid & 31;
    int m_base = blockIdx.x * 128;
    int m_off = (wid & 3) * 32, n_off = (wid >> 2) * 32;
    int gid = lane >> 2, tig = lane & 3;

    load_W(smem, SM_W0HI, SM_W0LO, g_Whi[0], g_Wlo[0], tid);
    split_A(smem, A4, scale, m_base, M, tid);
    __syncthreads();

    float acc[2][4][4];
    ZERO_ACC(acc);
    mma_merged(sb, SM_W0HI, SM_W0LO, m_off, n_off, lane, acc);

#pragma unroll
    for (int ni = 0; ni < 4; ni++) {
        int col = n_off + ni * 8 + tig * 2;
        float2 bb = *(const float2*)&bias[col];
#pragma unroll
        for (int mi = 0; mi < 2; mi++) {
            int r0 = m_base + m_off + mi * 16 + gid;
            float* c = acc[mi][ni];
            if (r0 < M)
                *(float2*)&C[(size_t)r0 * 128 + col] =
                    make_float2(fmaxf(c[0] + bb.x, 0.f), fmaxf(c[1] + bb.y, 0.f));
            if (r0 + 8 < M)
                *(float2*)&C[(size_t)(r0 + 8) * 128 + col] =
                    make_float2(fmaxf(c[2] + bb.x, 0.f), fmaxf(c[3] + bb.y, 0.f));
        }
    }
}

// ------------------------- fused h2 / P / Q (mma) ---------------------------
__global__ __launch_bounds__(GT)
void k_gemm3_mma(const float4* __restrict__ A4, const float* __restrict__ scale,
                 const float* __restrict__ b2, float* __restrict__ H2,
                 float* __restrict__ P, float* __restrict__ Q, int M) {
    extern __shared__ char smem[];
    uint32_t sb = smem_u32(smem);
    int tid = threadIdx.x, wid = tid >> 5, lane = tid & 31;
    int m_base = blockIdx.x * 128;
    int m_off = (wid & 3) * 32, n_off = (wid >> 2) * 32;
    int gid = lane >> 2, tig = lane & 3;

    float acc[2][4][4];

    // ---- phase 1: h2 = (t*deginv)@W2 + b2;  W1 slot preloaded with Wd1_bot
    load_W(smem, SM_W0HI, SM_W0LO, g_Whi[1], g_Wlo[1], tid);
    load_W(smem, SM_W1HI, SM_W1LO, g_Whi[3], g_Wlo[3], tid);
    split_A(smem, A4, scale, m_base, M, tid);
    __syncthreads();
    ZERO_ACC(acc);
    mma_merged(sb, SM_W0HI, SM_W0LO, m_off, n_off, lane, acc);
    __syncthreads();

    // epilogue: write H2, re-split h2 into A smem; load Wd1_top into W0
#pragma unroll
    for (int ni = 0; ni < 4; ni++) {
        int col = n_off + ni * 8 + tig * 2;
        float2 bb = *(const float2*)&b2[col];
#pragma unroll
        for (int mi = 0; mi < 2; mi++) {
            float* c = acc[mi][ni];
            float v0 = c[0] + bb.x, v1 = c[1] + bb.y;
            float v2 = c[2] + bb.x, v3 = c[3] + bb.y;
            int lr = m_off + mi * 16 + gid;
            int r0 = m_base + lr;
            if (r0 < M)     *(float2*)&H2[(size_t)r0 * 128 + col] = make_float2(v0, v1);
            if (r0 + 8 < M) *(float2*)&H2[(size_t)(r0 + 8) * 128 + col] = make_float2(v2, v3);
            float ra, rb;
            uint32_t hp0 = pack_hi2(v0, v1, ra, rb);
            uint32_t lp0 = pack_lo2(ra, rb);
            uint32_t hp1 = pack_hi2(v2, v3, ra, rb);
            uint32_t lp1 = pack_lo2(ra, rb);
            uint32_t o0 = lr * ROWB + col * 2;
            uint32_t o1 = (lr + 8) * ROWB + col * 2;
            *(uint32_t*)(smem + SM_AHI + o0) = hp0;
            *(uint32_t*)(smem + SM_ALO + o0) = lp0;
            *(uint32_t*)(smem + SM_AHI + o1) = hp1;
            *(uint32_t*)(smem + SM_ALO + o1) = lp1;
        }
    }
    load_W(smem, SM_W0HI, SM_W0LO, g_Whi[2], g_Wlo[2], tid);
    __syncthreads();

    // ---- phase 2: P = h2 @ Wd1_top ----
    ZERO_ACC(acc);
    mma_merged(sb, SM_W0HI, SM_W0LO, m_off, n_off, lane, acc);
#pragma unroll
    for (int ni = 0; ni < 4; ni++) {
        int col = n_off + ni * 8 + tig * 2;
#pragma unroll
        for (int mi = 0; mi < 2; mi++) {
            float* c = acc[mi][ni];
            int r0 = m_base + m_off + mi * 16 + gid;
            if (r0 < M)     *(float2*)&P[(size_t)r0 * 128 + col] = make_float2(c[0], c[1]);
            if (r0 + 8 < M) *(float2*)&P[(size_t)(r0 + 8) * 128 + col] = make_float2(c[2], c[3]);
        }
    }

    // ---- phase 3: Q = h2 @ Wd1_bot (preloaded; no barrier needed) ----
    ZERO_ACC(acc);
    mma_merged(sb, SM_W1HI, SM_W1LO, m_off, n_off, lane, acc);
#pragma unroll
    for (int ni = 0; ni < 4; ni++) {
        int col = n_off + ni * 8 + tig * 2;
#pragma unroll
        for (int mi = 0; mi < 2; mi++) {
            float* c = acc[mi][ni];
            int r0 = m_base + m_off + mi * 16 + gid;
            if (r0 < M)     *(float2*)&Q[(size_t)r0 * 128 + col] = make_float2(c[0], c[1]);
            if (r0 + 8 < M) *(float2*)&Q[(size_t)(r0 + 8) * 128 + col] = make_float2(c[2], c[3]);
        }
    }
}

// -------------------------------- graph prep -------------------------------
__global__ void k_build(const int2* __restrict__ idx, const float* __restrict__ val, int ne) {
    int e = blockIdx.x * blockDim.x + threadIdx.x;
    if (e >= ne) return;
    int2 rc = idx[e];
    float v = val[e];
    int slot = atomicAdd(&g_cnt[rc.x], 1);
    if (slot < CAP) {
        g_col[rc.x * CAP + slot] = rc.y;
        g_val[rc.x * CAP + slot] = v;
    }
}

__global__ void k_spmm(const float4* __restrict__ X, float4* __restrict__ Y,
                       float* __restrict__ deginv_out, int nn) {
    int w = (blockIdx.x * blockDim.x + threadIdx.x) >> 5;
    int lane = threadIdx.x & 31;
    if (w >= nn) return;
    int cnt = g_cnt[w];
    if (cnt > CAP) cnt = CAP;
    const int*   cols = &g_col[w * CAP];
    const float* vals = &g_val[w * CAP];
    float4 acc = make_float4(0.f, 0.f, 0.f, 0.f);
    float dsum = 0.f;
#pragma unroll 2
    for (int e = 0; e < cnt; e++) {
        int c = cols[e];
        float v = vals[e];
        float4 x = X[(size_t)c * 32 + lane];
        acc.x += v * x.x; acc.y += v * x.y; acc.z += v * x.z; acc.w += v * x.w;
        dsum += v;
    }
    Y[(size_t)w * 32 + lane] = acc;
    if (deginv_out != nullptr && lane == 0)
        deginv_out[w] = 1.0f / fmaxf(dsum, 1.0f);
}

// -------------------------------- decoder ----------------------------------
__global__ void k_decode2(const int* __restrict__ pu, const int* __restrict__ pv,
                          const int* __restrict__ nu, const int* __restrict__ nv,
                          const float4* __restrict__ P, const float4* __restrict__ Q,
                          const float* __restrict__ bd1, const float* __restrict__ Wd2,
                          const float* __restrict__ bd2, float* __restrict__ out, int NP) {
    int w = (blockIdx.x * blockDim.x + threadIdx.x) >> 5;
    int lane = threadIdx.x & 31;
    if (w >= 2 * NP) return;
    int u, v;
    if (w < NP) { u = pu[w]; v = pv[w]; }
    else        { u = nu[w - NP]; v = nv[w - NP]; }
    float4 p = P[(size_t)u * 32 + lane];
    float4 q = Q[(size_t)v * 32 + lane];
    float4 b = ((const float4*)bd1)[lane];
    float4 d = ((const float4*)Wd2)[lane];
    float h0 = fmaxf(p.x + q.x + b.x, 0.f);
    float h1 = fmaxf(p.y + q.y + b.y, 0.f);
    float h2 = fmaxf(p.z + q.z + b.z, 0.f);
    float h3 = fmaxf(p.w + q.w + b.w, 0.f);
    float s = h0 * d.x + h1 * d.y + h2 * d.z + h3 * d.w;
#pragma unroll
    for (int o = 16; o > 0; o >>= 1)
        s += __shfl_down_sync(0xffffffff, s, o);
    if (lane == 0) out[w] = s + bd2[0];
}

// -------------------------------- launcher ---------------------------------
extern "C" void kernel_launch(void* const* d_in, const int* in_sizes, int n_in,
                              void* d_out, int out_size) {
    int o = (n_in >= 16) ? 1 : 0;

    const int2*  adj   = (const int2*) d_in[0];
    const float* avals = (const float*)d_in[1];
    const float* h     = (const float*)d_in[2 + o];
    const int*   pos_u = (const int*)  d_in[3 + o];
    const int*   pos_v = (const int*)  d_in[4 + o];
    const int*   neg_u = (const int*)  d_in[5 + o];
    const int*   neg_v = (const int*)  d_in[6 + o];
    const float* W1    = (const float*)d_in[7 + o];
    const float* b1    = (const float*)d_in[8 + o];
    const float* W2    = (const float*)d_in[9 + o];
    const float* b2    = (const float*)d_in[10 + o];
    const float* Wd1   = (const float*)d_in[11 + o];
    const float* bd1   = (const float*)d_in[12 + o];
    const float* Wd2   = (const float*)d_in[13 + o];
    const float* bd2   = (const float*)d_in[14 + o];

    const int NE = in_sizes[1];
    const int NN = in_sizes[2 + o] / 128;
    const int NP = in_sizes[3 + o];

    float* out = (float*)d_out;
    float* pos_out = out;
    float* h2      = out + 2 * NP;

    static float* p_t = nullptr;
    static float* p_h1 = nullptr;
    static float* p_P = nullptr;
    static float* p_Q = nullptr;
    static float* p_deginv = nullptr;
    static int*   p_cnt = nullptr;
    static bool init = false;
    if (!init) {
        cudaGetSymbolAddress((void**)&p_t, g_t);
        cudaGetSymbolAddress((void**)&p_h1, g_h1);
        cudaGetSymbolAddress((void**)&p_P, g_P);
        cudaGetSymbolAddress((void**)&p_Q, g_Q);
        cudaGetSymbolAddress((void**)&p_deginv, g_deginv);
        cudaGetSymbolAddress((void**)&p_cnt, g_cnt);
        cudaFuncSetAttribute(k_gemm1_mma, cudaFuncAttributeMaxDynamicSharedMemorySize, SMEM_G1);
        cudaFuncSetAttribute(k_gemm3_mma, cudaFuncAttributeMaxDynamicSharedMemorySize, SMEM_G3);
        init = true;
    }

    int tcg = (NN + 127) / 128;

    cudaMemsetAsync(p_cnt, 0, (size_t)NN * sizeof(int));
    k_build<<<(NE + 255) / 256, 256>>>(adj, avals, NE);
    k_prep<<<(4 * 16384 + 255) / 256, 256>>>(W1, W2, Wd1);
    k_spmm<<<(NN * 32 + 255) / 256, 256>>>((const float4*)h, (float4*)p_t, p_deginv, NN);
    k_gemm1_mma<<<tcg, GT, SMEM_G1>>>((const float4*)p_t, p_deginv, b1, p_h1, NN);
    k_spmm<<<(NN * 32 + 255) / 256, 256>>>((const float4*)p_h1, (float4*)p_t, nullptr, NN);
    k_gemm3_mma<<<tcg, GT, SMEM_G3>>>((const float4*)p_t, p_deginv, b2, h2, p_P, p_Q, NN);
    k_decode2<<<(2 * NP * 32 + 255) / 256, 256>>>(pos_u, pos_v, neg_u, neg_v,
                                                  (const float4*)p_P, (const float4*)p_Q,
                                                  bd1, Wd2, bd2, pos_out, NP);
}